// round 3
// baseline (speedup 1.0000x reference)
#include <cuda_runtime.h>
#include <math.h>

#define BSZ 2
#define TSZ 2048
#define DSZ 512
#define HSZ 8
#define CSZ 64
#define WINSZ 128
#define MROWS (BSZ*TSZ)   // 4096

// Scratch (device globals: no allocation allowed)
__device__ float g_q[BSZ*TSZ*HSZ*CSZ];
__device__ float g_k[BSZ*TSZ*HSZ*CSZ];
__device__ float g_v[BSZ*TSZ*HSZ*CSZ];
__device__ float g_att[BSZ*TSZ*HSZ*CSZ];

// ---------------------------------------------------------------------------
// Classic 128x128x8 register-blocked fp32 GEMM body: C = A(MxK) @ B(KxN)
// 256 threads, 8x8 accum per thread. M,N multiples of 128; K multiple of 8.
// ---------------------------------------------------------------------------
__device__ __forceinline__ void sgemm_body(const float* __restrict__ A,
                                           const float* __restrict__ Bm,
                                           float* __restrict__ C,
                                           int M, int N, int K)
{
    __shared__ float As[8][128];
    __shared__ float Bs[8][128];

    const int tid = threadIdx.x;
    const int tx = tid & 15;         // 0..15 -> 8 cols each
    const int ty = tid >> 4;         // 0..15 -> 8 rows each
    const int m0 = blockIdx.y * 128;
    const int n0 = blockIdx.x * 128;

    const int aRow = tid >> 1;           // 0..127
    const int aCol = (tid & 1) * 4;      // 0 or 4
    const int bRow = tid >> 5;           // 0..7
    const int bCol = (tid & 31) * 4;     // 0..124

    float acc[8][8];
#pragma unroll
    for (int i = 0; i < 8; i++)
#pragma unroll
        for (int j = 0; j < 8; j++) acc[i][j] = 0.f;

    for (int k0 = 0; k0 < K; k0 += 8) {
        float4 av = *(const float4*)&A[(size_t)(m0 + aRow) * K + k0 + aCol];
        As[aCol + 0][aRow] = av.x;
        As[aCol + 1][aRow] = av.y;
        As[aCol + 2][aRow] = av.z;
        As[aCol + 3][aRow] = av.w;
        float4 bv = *(const float4*)&Bm[(size_t)(k0 + bRow) * N + n0 + bCol];
        *(float4*)&Bs[bRow][bCol] = bv;
        __syncthreads();

#pragma unroll
        for (int kk = 0; kk < 8; kk++) {
            float a[8], b[8];
            *(float4*)&a[0] = *(float4*)&As[kk][ty * 8];
            *(float4*)&a[4] = *(float4*)&As[kk][ty * 8 + 4];
            *(float4*)&b[0] = *(float4*)&Bs[kk][tx * 8];
            *(float4*)&b[4] = *(float4*)&Bs[kk][tx * 8 + 4];
#pragma unroll
            for (int i = 0; i < 8; i++)
#pragma unroll
                for (int j = 0; j < 8; j++)
                    acc[i][j] = fmaf(a[i], b[j], acc[i][j]);
        }
        __syncthreads();
    }

#pragma unroll
    for (int i = 0; i < 8; i++) {
        float* crow = &C[(size_t)(m0 + ty * 8 + i) * N + n0 + tx * 8];
        *(float4*)&crow[0] = make_float4(acc[i][0], acc[i][1], acc[i][2], acc[i][3]);
        *(float4*)&crow[4] = make_float4(acc[i][4], acc[i][5], acc[i][6], acc[i][7]);
    }
}

__global__ void __launch_bounds__(256)
qkv_gemm(const float* __restrict__ A,
         const float* __restrict__ Wq,
         const float* __restrict__ Wk,
         const float* __restrict__ Wv)
{
    const float* W = (blockIdx.z == 0) ? Wq : (blockIdx.z == 1) ? Wk : Wv;
    float* C = (blockIdx.z == 0) ? g_q : (blockIdx.z == 1) ? g_k : g_v;
    sgemm_body(A, W, C, MROWS, HSZ * CSZ, DSZ);
}

__global__ void __launch_bounds__(256)
out_gemm(const float* __restrict__ Wo, float* __restrict__ out)
{
    sgemm_body(g_att, Wo, out, MROWS, DSZ, HSZ * CSZ);
}

// ---------------------------------------------------------------------------
// RMSNorm + RoPE, one warp per (b,t,h) head vector of C=64.
// Lane handles c=lane and c=lane+32. blockIdx.y: 0 -> q, 1 -> k.
// ---------------------------------------------------------------------------
__global__ void __launch_bounds__(256)
norm_rope(const float* __restrict__ cosT, const float* __restrict__ sinT,
          const float* __restrict__ qw, const float* __restrict__ kw)
{
    int w = blockIdx.x * 8 + (threadIdx.x >> 5);   // linear (b,t,h)
    int lane = threadIdx.x & 31;
    int t = (w / HSZ) % TSZ;

    float* x = ((blockIdx.y == 0) ? g_q : g_k) + (size_t)w * CSZ;
    const float* wgt = (blockIdx.y == 0) ? qw : kw;

    float x0 = x[lane];
    float x1 = x[lane + 32];
    float ss = x0 * x0 + x1 * x1;
#pragma unroll
    for (int o = 16; o; o >>= 1) ss += __shfl_xor_sync(0xffffffffu, ss, o);
    float nrm = rsqrtf(ss * (1.f / CSZ) + 1e-6f);
    float y0 = x0 * nrm * wgt[lane];
    float y1 = x1 * nrm * wgt[lane + 32];

    float c0 = cosT[t * CSZ + lane];
    float c1 = cosT[t * CSZ + lane + 32];
    float s0 = sinT[t * CSZ + lane];
    float s1 = sinT[t * CSZ + lane + 32];
    // rotated = [-x2, x1]
    x[lane]      = y0 * c0 - y1 * s0;
    x[lane + 32] = y1 * c1 + y0 * s1;
}

// ---------------------------------------------------------------------------
// Sliding-window attention. Block = (b, h, 32 queries). 8 warps, each warp
// owns 4 queries. Keys streamed in 3 chunks of 64 covering [t0-128, t0+63].
// Online softmax; accumulators in registers (lane c and c+32).
// ---------------------------------------------------------------------------
__global__ void __launch_bounds__(256)
attn_kernel()
{
    __shared__ float Qs[32][65];
    __shared__ float Ks[64][65];
    __shared__ float Vs[64][65];

    const int b = blockIdx.z, h = blockIdx.y;
    const int t0 = blockIdx.x * 32;
    const int tid = threadIdx.x;
    const int lane = tid & 31;
    const int w = tid >> 5;

    // load Q tile (32 x 64)
    for (int idx = tid; idx < 32 * 16; idx += 256) {
        int r = idx >> 4, c4 = (idx & 15) * 4;
        float4 v = *(const float4*)&g_q[(((size_t)(b * TSZ + t0 + r) * HSZ) + h) * CSZ + c4];
        Qs[r][c4 + 0] = v.x; Qs[r][c4 + 1] = v.y; Qs[r][c4 + 2] = v.z; Qs[r][c4 + 3] = v.w;
    }

    float m[4], l[4], o0[4], o1[4];
#pragma unroll
    for (int q = 0; q < 4; q++) { m[q] = -INFINITY; l[q] = 0.f; o0[q] = 0.f; o1[q] = 0.f; }

    for (int ch = 0; ch < 3; ch++) {
        int s_base = t0 - 128 + ch * 64;
        // load K,V chunk (64 x 64 each)
        for (int idx = tid; idx < 64 * 16; idx += 256) {
            int r = idx >> 4, c4 = (idx & 15) * 4;
            int s = s_base + r;
            float4 kv = make_float4(0.f, 0.f, 0.f, 0.f), vv = kv;
            if (s >= 0 && s < TSZ) {
                size_t base = (((size_t)(b * TSZ + s) * HSZ) + h) * CSZ + c4;
                kv = *(const float4*)&g_k[base];
                vv = *(const float4*)&g_v[base];
            }
            Ks[r][c4 + 0] = kv.x; Ks[r][c4 + 1] = kv.y; Ks[r][c4 + 2] = kv.z; Ks[r][c4 + 3] = kv.w;
            Vs[r][c4 + 0] = vv.x; Vs[r][c4 + 1] = vv.y; Vs[r][c4 + 2] = vv.z; Vs[r][c4 + 3] = vv.w;
        }
        __syncthreads();

#pragma unroll
        for (int q = 0; q < 4; q++) {
            const int qi = w * 4 + q;
            const int i = t0 + qi;
            float acc0 = 0.f, acc1 = 0.f;
#pragma unroll
            for (int c = 0; c < 64; c++) {
                float qv = Qs[qi][c];
                acc0 = fmaf(qv, Ks[lane][c], acc0);
                acc1 = fmaf(qv, Ks[lane + 32][c], acc1);
            }
            int s0g = s_base + lane, s1g = s_base + lane + 32;
            float l0 = (s0g >= 0 && s0g <= i && s0g > i - WINSZ) ? acc0 * 0.125f : -INFINITY;
            float l1 = (s1g >= 0 && s1g <= i && s1g > i - WINSZ) ? acc1 * 0.125f : -INFINITY;
            float cm = fmaxf(l0, l1);
#pragma unroll
            for (int o = 16; o; o >>= 1) cm = fmaxf(cm, __shfl_xor_sync(0xffffffffu, cm, o));
            float mn = fmaxf(m[q], cm);
            if (mn == -INFINITY) continue;   // warp-uniform: chunk fully masked

            float scale = expf(m[q] - mn);
            float p0 = expf(l0 - mn);
            float p1 = expf(l1 - mn);
            float psum = p0 + p1;
#pragma unroll
            for (int o = 16; o; o >>= 1) psum += __shfl_xor_sync(0xffffffffu, psum, o);
            l[q] = l[q] * scale + psum;
            o0[q] *= scale;
            o1[q] *= scale;
#pragma unroll
            for (int s2 = 0; s2 < 32; s2++) {
                float p = __shfl_sync(0xffffffffu, p0, s2);
                o0[q] = fmaf(p, Vs[s2][lane], o0[q]);
                o1[q] = fmaf(p, Vs[s2][lane + 32], o1[q]);
            }
#pragma unroll
            for (int s2 = 0; s2 < 32; s2++) {
                float p = __shfl_sync(0xffffffffu, p1, s2);
                o0[q] = fmaf(p, Vs[s2 + 32][lane], o0[q]);
                o1[q] = fmaf(p, Vs[s2 + 32][lane + 32], o1[q]);
            }
            m[q] = mn;
        }
        __syncthreads();
    }

#pragma unroll
    for (int q = 0; q < 4; q++) {
        int i = t0 + w * 4 + q;
        float inv = 1.f / l[q];
        size_t base = (((size_t)(b * TSZ + i) * HSZ) + h) * CSZ;
        g_att[base + lane]      = o0[q] * inv;
        g_att[base + lane + 32] = o1[q] * inv;
    }
}

// ---------------------------------------------------------------------------
extern "C" void kernel_launch(void* const* d_in, const int* in_sizes, int n_in,
                              void* d_out, int out_size)
{
    const float* h        = (const float*)d_in[0];
    const float* rope_cos = (const float*)d_in[1];
    const float* rope_sin = (const float*)d_in[2];
    const float* W_q      = (const float*)d_in[3];
    const float* W_k      = (const float*)d_in[4];
    const float* W_v      = (const float*)d_in[5];
    const float* W_o      = (const float*)d_in[6];
    const float* q_norm_w = (const float*)d_in[7];
    const float* k_norm_w = (const float*)d_in[8];
    float* out = (float*)d_out;

    dim3 gQKV(DSZ / 128, MROWS / 128, 3);           // (4, 32, 3)
    qkv_gemm<<<gQKV, 256>>>(h, W_q, W_k, W_v);

    dim3 gNR(BSZ * TSZ * HSZ / 8, 2);               // (4096, 2)
    norm_rope<<<gNR, 256>>>(rope_cos, rope_sin, q_norm_w, k_norm_w);

    dim3 gAtt(TSZ / 32, HSZ, BSZ);                  // (64, 8, 2)
    attn_kernel<<<gAtt, 256>>>();

    dim3 gO(DSZ / 128, MROWS / 128);                // (4, 32)
    out_gemm<<<gO, 256>>>(W_o, out);
}